// round 1
// baseline (speedup 1.0000x reference)
#include <cuda_runtime.h>
#include <math.h>

// ---------------- problem constants ----------------
#define NENT   200000
#define NREL   500
#define NNODES 100000
#define NNEW   50000
#define MEDGE  200000
#define EDIM   128
#define HDIM   256
#define QDIM   256
#define BDIM   256

// ---------------- device scratch (no allocations allowed) ----------------
__device__ float g_relWr [NREL * HDIM];        // relation_emb @ Wr
__device__ float g_relWqr[NREL * HDIM];        // relation_emb @ Wqr
__device__ float g_relC2 [NREL * HDIM];        // relation_emb @ cand_W[E:2E] + cand_b
__device__ float g_qdot  [BDIM];               // query_repr @ rank_W[H:]
__device__ float g_NHW   [(size_t)NNODES * HDIM]; // node_hidden @ Ws
__device__ float g_EW1   [(size_t)NENT   * HDIM]; // entity_emb @ cand_W[0:E]
__device__ float g_agg   [(size_t)NNEW * 2 * EDIM];
__device__ float g_hprev [(size_t)NNEW * HDIM];
__device__ float g_GX    [(size_t)NNEW * 3 * HDIM];
__device__ float g_GH    [(size_t)NNEW * 3 * HDIM];
__device__ float g_hnew  [(size_t)NNEW * HDIM];
__device__ float g_HN3   [(size_t)NNEW * HDIM];

// ---------------- generic 128x128x8 SGEMM ----------------
// C[M,N] = op(A[M,K] (optionally row-gathered) @ B)      (fp32)
// BT=false: B is [K,N] row-major.  BT=true: B is [N,K] row-major (use B^T).
// EPI: 0 = none, 1 = +bias[col], 2 = leaky_relu(x + bias[col], 0.01)
template <int EPI, bool BT, bool GATHER>
__global__ __launch_bounds__(256)
void sgemm128(const float* __restrict__ A, const float* __restrict__ Bm,
              const float* __restrict__ bias, float* __restrict__ C,
              int Mrows, int K, int N, const int* __restrict__ gidx)
{
    __shared__ float As[8][128];
    __shared__ float Bs[8][128];

    const int tid = threadIdx.x;
    const int bx = blockIdx.x, by = blockIdx.y;
    const int tx = tid & 15, ty = tid >> 4;

    // ---- A tile load coords (128 rows x 8 k, one float4/thread) ----
    const int arow = tid >> 1;
    const int acol = (tid & 1) * 4;
    const int grow = by * 128 + arow;
    const bool avalid = (grow < Mrows);
    size_t arow_phys = 0;
    if (avalid) arow_phys = GATHER ? (size_t)gidx[grow] : (size_t)grow;
    const float* Aptr = A + arow_phys * (size_t)K + acol;

    // ---- B tile load coords ----
    int bj = 0, bk4 = 0, brow = 0, bcol = 0;
    const float* Bptr;
    if (BT) {
        bj  = tid >> 1;
        bk4 = (tid & 1) * 4;
        Bptr = Bm + (size_t)(bx * 128 + bj) * K + bk4;
    } else {
        brow = tid >> 5;           // 0..7
        bcol = (tid & 31) * 4;     // 0..124
        Bptr = Bm + (size_t)brow * N + bx * 128 + bcol;
    }

    float acc[8][8];
#pragma unroll
    for (int i = 0; i < 8; i++)
#pragma unroll
        for (int j = 0; j < 8; j++) acc[i][j] = 0.f;

    const int ktiles = K >> 3;
    const float4 z4 = make_float4(0.f, 0.f, 0.f, 0.f);
    float4 aval = avalid ? *(const float4*)Aptr : z4;
    float4 bval = *(const float4*)Bptr;

    int kt = 0;
    for (;;) {
        As[acol + 0][arow] = aval.x;
        As[acol + 1][arow] = aval.y;
        As[acol + 2][arow] = aval.z;
        As[acol + 3][arow] = aval.w;
        if (BT) {
            Bs[bk4 + 0][bj] = bval.x;
            Bs[bk4 + 1][bj] = bval.y;
            Bs[bk4 + 2][bj] = bval.z;
            Bs[bk4 + 3][bj] = bval.w;
        } else {
            *(float4*)&Bs[brow][bcol] = bval;
        }
        __syncthreads();

        kt++;
        if (kt < ktiles) {   // prefetch next tile into registers
            aval = avalid ? *(const float4*)(Aptr + kt * 8) : z4;
            bval = BT ? *(const float4*)(Bptr + kt * 8)
                      : *(const float4*)(Bptr + (size_t)kt * 8 * N);
        }

#pragma unroll
        for (int k = 0; k < 8; k++) {
            float ar[8], br[8];
            *(float4*)&ar[0] = *(const float4*)&As[k][ty * 4];
            *(float4*)&ar[4] = *(const float4*)&As[k][64 + ty * 4];
            *(float4*)&br[0] = *(const float4*)&Bs[k][tx * 4];
            *(float4*)&br[4] = *(const float4*)&Bs[k][64 + tx * 4];
#pragma unroll
            for (int i = 0; i < 8; i++)
#pragma unroll
                for (int j = 0; j < 8; j++)
                    acc[i][j] = fmaf(ar[i], br[j], acc[i][j]);
        }
        if (kt >= ktiles) break;
        __syncthreads();
    }

    // ---- epilogue + store ----
#pragma unroll
    for (int ih = 0; ih < 2; ih++) {
#pragma unroll
        for (int i = 0; i < 4; i++) {
            int r = by * 128 + ih * 64 + ty * 4 + i;
            if (r >= Mrows) continue;
#pragma unroll
            for (int jh = 0; jh < 2; jh++) {
                int col = bx * 128 + jh * 64 + tx * 4;
                float v[4];
#pragma unroll
                for (int u = 0; u < 4; u++) {
                    float x = acc[ih * 4 + i][jh * 4 + u];
                    if (EPI >= 1) x += bias[col + u];
                    if (EPI == 2) x = (x > 0.f) ? x : 0.01f * x;
                    v[u] = x;
                }
                *(float4*)&C[(size_t)r * N + col] = *(float4*)v;
            }
        }
    }
}

// ---------------- small precompute kernels ----------------
__global__ void rel_precompute(const float* __restrict__ rel_emb,
                               const float* __restrict__ Wr,
                               const float* __restrict__ Wqr,
                               const float* __restrict__ candW,
                               const float* __restrict__ cand_b)
{
    const int r = blockIdx.x;
    const int j = threadIdx.x;       // 256 threads
    __shared__ float re[EDIM];
    if (j < EDIM) re[j] = rel_emb[r * EDIM + j];
    __syncthreads();
    float s1 = 0.f, s2 = 0.f, s3 = 0.f;
#pragma unroll 4
    for (int k = 0; k < EDIM; k++) {
        const float rv = re[k];
        s1 = fmaf(rv, Wr[k * HDIM + j], s1);
        s2 = fmaf(rv, Wqr[k * HDIM + j], s2);
        s3 = fmaf(rv, candW[(EDIM + k) * HDIM + j], s3);
    }
    g_relWr[r * HDIM + j]  = s1;
    g_relWqr[r * HDIM + j] = s2;
    g_relC2[r * HDIM + j]  = s3 + cand_b[j];
}

__global__ void qdot_kernel(const float* __restrict__ qrep,
                            const float* __restrict__ rankW)
{
    const int b = blockIdx.x * 8 + (threadIdx.x >> 5);
    const int lane = threadIdx.x & 31;
    if (b >= BDIM) return;
    float s = 0.f;
#pragma unroll
    for (int i = 0; i < 8; i++) {
        int q = lane + 32 * i;
        s = fmaf(qrep[b * QDIM + q], rankW[HDIM + q], s);
    }
#pragma unroll
    for (int o = 16; o > 0; o >>= 1) s += __shfl_xor_sync(0xffffffffu, s, o);
    if (lane == 0) g_qdot[b] = s;
}

__global__ void zero_agg_kernel()
{
    const size_t n4 = (size_t)NNEW * 2 * EDIM / 4;
    size_t i = (size_t)blockIdx.x * blockDim.x + threadIdx.x;
    if (i < n4) ((float4*)g_agg)[i] = make_float4(0.f, 0.f, 0.f, 0.f);
}

// ---------------- per-edge attention + scatter ----------------
__global__ __launch_bounds__(256)
void edge_alpha_scatter(const float* __restrict__ rel_emb,
                        const float* __restrict__ ent_emb,
                        const float* __restrict__ bqr,
                        const float* __restrict__ w_alpha,
                        const float* __restrict__ b_alpha,
                        const int* __restrict__ head,
                        const int* __restrict__ erel,
                        const int* __restrict__ qrel,
                        const int* __restrict__ tent,
                        const int* __restrict__ tnode)
{
    const int m = blockIdx.x * 8 + (threadIdx.x >> 5);
    if (m >= MEDGE) return;
    const int lane = threadIdx.x & 31;
    const int h = head[m], r = erel[m], q = qrel[m];
    const int te = tent[m], t = tnode[m];

    const float* nh = g_NHW   + (size_t)h * HDIM;
    const float* rw = g_relWr + r * HDIM;
    const float* rq = g_relWqr + q * HDIM;

    float s = 0.f;
#pragma unroll
    for (int i = 0; i < 8; i++) {
        int j = lane + 32 * i;
        float f = nh[j] + rw[j] + rq[j] + bqr[j];
        f = fmaxf(f, 0.f);
        s = fmaf(f, w_alpha[j], s);
    }
#pragma unroll
    for (int o = 16; o > 0; o >>= 1) s += __shfl_xor_sync(0xffffffffu, s, o);
    const float alpha = 1.f / (1.f + __expf(-(s + b_alpha[0])));

    const float* hr  = rel_emb + r * EDIM;
    const float* tev = ent_emb + (size_t)te * EDIM;
    float* aggp = g_agg + (size_t)t * (2 * EDIM);
#pragma unroll
    for (int i = 0; i < 4; i++) {
        int j = lane + 32 * i;
        atomicAdd(&aggp[j],        hr[j]  * alpha);
        atomicAdd(&aggp[EDIM + j], tev[j] * alpha);
    }
}

// ---------------- GRU gates + LayerNorm (one block per node) ----------------
__global__ __launch_bounds__(256)
void gru_ln_kernel(const float* __restrict__ ln_g, const float* __restrict__ ln_b)
{
    const int n = blockIdx.x;
    const int j = threadIdx.x;
    const size_t o3 = (size_t)n * 3 * HDIM;

    const float xr = g_GX[o3 + j];
    const float xz = g_GX[o3 + HDIM + j];
    const float xn = g_GX[o3 + 2 * HDIM + j];
    const float hr = g_GH[o3 + j];
    const float hz = g_GH[o3 + HDIM + j];
    const float hn = g_GH[o3 + 2 * HDIM + j];
    const float hp = g_hprev[(size_t)n * HDIM + j];

    const float rg = 1.f / (1.f + __expf(-(xr + hr)));
    const float zg = 1.f / (1.f + __expf(-(xz + hz)));
    const float ng = tanhf(xn + rg * hn);
    const float h  = (1.f - zg) * ng + zg * hp;

    // block LayerNorm over 256
    __shared__ float rs1[8], rs2[8];
    float s1 = h, s2 = h * h;
#pragma unroll
    for (int o = 16; o > 0; o >>= 1) {
        s1 += __shfl_xor_sync(0xffffffffu, s1, o);
        s2 += __shfl_xor_sync(0xffffffffu, s2, o);
    }
    const int wid = threadIdx.x >> 5, lane = threadIdx.x & 31;
    if (lane == 0) { rs1[wid] = s1; rs2[wid] = s2; }
    __syncthreads();
    if (wid == 0) {
        float a = (lane < 8) ? rs1[lane] : 0.f;
        float b = (lane < 8) ? rs2[lane] : 0.f;
#pragma unroll
        for (int o = 4; o > 0; o >>= 1) {
            a += __shfl_xor_sync(0xffffffffu, a, o);
            b += __shfl_xor_sync(0xffffffffu, b, o);
        }
        if (lane == 0) { rs1[0] = a; rs2[0] = b; }
    }
    __syncthreads();
    const float mu  = rs1[0] * (1.f / HDIM);
    const float var = rs2[0] * (1.f / HDIM) - mu * mu;
    const float inv = rsqrtf(var + 1e-5f);
    g_hnew[(size_t)n * HDIM + j] = (h - mu) * inv * ln_g[j] + ln_b[j];
}

// ---------------- final per-edge scoring ----------------
__global__ __launch_bounds__(256)
void edge_score(const int* __restrict__ erel,
                const int* __restrict__ tent,
                const int* __restrict__ tnode,
                const int* __restrict__ bidx,
                const float* __restrict__ rankW,
                const float* __restrict__ rank_b,
                float* __restrict__ out)
{
    const int m = blockIdx.x * 8 + (threadIdx.x >> 5);
    if (m >= MEDGE) return;
    const int lane = threadIdx.x & 31;
    const int r = erel[m], te = tent[m], t = tnode[m], b = bidx[m];

    const float* e1 = g_EW1   + (size_t)te * HDIM;
    const float* c2 = g_relC2 + r * HDIM;
    const float* h3 = g_HN3   + (size_t)t * HDIM;

    float s = 0.f;
#pragma unroll
    for (int i = 0; i < 8; i++) {
        int j = lane + 32 * i;
        float v = e1[j] + c2[j] + h3[j];
        v = (v > 0.f) ? v : 0.01f * v;   // leaky_relu
        s = fmaf(v, rankW[j], s);
    }
#pragma unroll
    for (int o = 16; o > 0; o >>= 1) s += __shfl_xor_sync(0xffffffffu, s, o);
    if (lane == 0) out[m] = s + g_qdot[b] + rank_b[0];
}

// ---------------- launcher ----------------
extern "C" void kernel_launch(void* const* d_in, const int* in_sizes, int n_in,
                              void* d_out, int out_size)
{
    const float* entity_emb   = (const float*)d_in[0];
    const float* relation_emb = (const float*)d_in[1];
    const float* node_hidden  = (const float*)d_in[2];
    const float* query_repr   = (const float*)d_in[3];
    const float* Ws           = (const float*)d_in[4];
    const float* Wr           = (const float*)d_in[5];
    const float* Wqr          = (const float*)d_in[6];
    const float* bqr          = (const float*)d_in[7];
    const float* w_alpha      = (const float*)d_in[8];
    const float* b_alpha      = (const float*)d_in[9];
    const float* W_ih         = (const float*)d_in[10];
    const float* W_hh         = (const float*)d_in[11];
    const float* b_ih         = (const float*)d_in[12];
    const float* b_hh         = (const float*)d_in[13];
    const float* We2h_W       = (const float*)d_in[14];
    const float* We2h_b       = (const float*)d_in[15];
    const float* cand_W       = (const float*)d_in[16];
    const float* cand_b       = (const float*)d_in[17];
    const float* rank_W       = (const float*)d_in[18];
    const float* rank_b       = (const float*)d_in[19];
    const float* ln_g         = (const float*)d_in[20];
    const float* ln_b         = (const float*)d_in[21];
    const int* head_node      = (const int*)d_in[22];
    const int* edge_rel       = (const int*)d_in[23];
    const int* tail_ent       = (const int*)d_in[24];
    const int* tail_node      = (const int*)d_in[25];
    const int* query_rel      = (const int*)d_in[26];
    const int* batch_idx      = (const int*)d_in[27];
    const int* tail_node_ent  = (const int*)d_in[28];
    float* scores = (float*)d_out;

    float *p_NHW, *p_EW1, *p_agg, *p_hprev, *p_GX, *p_GH, *p_hnew, *p_HN3;
    cudaGetSymbolAddress((void**)&p_NHW,   g_NHW);
    cudaGetSymbolAddress((void**)&p_EW1,   g_EW1);
    cudaGetSymbolAddress((void**)&p_agg,   g_agg);
    cudaGetSymbolAddress((void**)&p_hprev, g_hprev);
    cudaGetSymbolAddress((void**)&p_GX,    g_GX);
    cudaGetSymbolAddress((void**)&p_GH,    g_GH);
    cudaGetSymbolAddress((void**)&p_hnew,  g_hnew);
    cudaGetSymbolAddress((void**)&p_HN3,   g_HN3);

    // 1. independent precompute
    zero_agg_kernel<<<(NNEW * 2 * EDIM / 4 + 255) / 256, 256>>>();
    rel_precompute<<<NREL, 256>>>(relation_emb, Wr, Wqr, cand_W, cand_b);
    qdot_kernel<<<BDIM / 8, 256>>>(query_repr, rank_W);

    // NHW = node_hidden @ Ws            [100000,256] x [256,256]
    sgemm128<0, false, false><<<dim3(2, (NNODES + 127) / 128), 256>>>(
        node_hidden, Ws, nullptr, p_NHW, NNODES, HDIM, HDIM, nullptr);
    // EW1 = entity_emb @ cand_W[0:E]    [200000,128] x [128,256]
    sgemm128<0, false, false><<<dim3(2, (NENT + 127) / 128), 256>>>(
        entity_emb, cand_W, nullptr, p_EW1, NENT, EDIM, HDIM, nullptr);
    // h_prev = lrelu(gather(entity_emb, tail_node_ent) @ We2h + b)
    sgemm128<2, false, true><<<dim3(2, (NNEW + 127) / 128), 256>>>(
        entity_emb, We2h_W, We2h_b, p_hprev, NNEW, EDIM, HDIM, tail_node_ent);

    // 2. per-edge attention + scatter into agg
    edge_alpha_scatter<<<(MEDGE + 7) / 8, 256>>>(
        relation_emb, entity_emb, bqr, w_alpha, b_alpha,
        head_node, edge_rel, query_rel, tail_ent, tail_node);

    // 3. GRU input/hidden GEMMs  (B transposed: torch [3H, in] layout)
    sgemm128<1, true, false><<<dim3(6, (NNEW + 127) / 128), 256>>>(
        p_agg, W_ih, b_ih, p_GX, NNEW, 2 * EDIM, 3 * HDIM, nullptr);
    sgemm128<1, true, false><<<dim3(6, (NNEW + 127) / 128), 256>>>(
        p_hprev, W_hh, b_hh, p_GH, NNEW, HDIM, 3 * HDIM, nullptr);

    // 4. gates + LayerNorm
    gru_ln_kernel<<<NNEW, 256>>>(ln_g, ln_b);

    // 5. HN3 = h_new @ cand_W[2E:2E+H]
    sgemm128<0, false, false><<<dim3(2, (NNEW + 127) / 128), 256>>>(
        p_hnew, cand_W + 2 * EDIM * HDIM, nullptr, p_HN3, NNEW, HDIM, HDIM, nullptr);

    // 6. final scores
    edge_score<<<(MEDGE + 7) / 8, 256>>>(
        edge_rel, tail_ent, tail_node, batch_idx, rank_W, rank_b, scores);
}

// round 3
// speedup vs baseline: 1.8599x; 1.8599x over previous
#include <cuda_runtime.h>
#include <cuda_bf16.h>
#include <math.h>
#include <stdint.h>

// ---------------- problem constants ----------------
#define NENT   200000
#define NREL   500
#define NNODES 100000
#define NNEW   50000
#define MEDGE  200000
#define EDIM   128
#define HDIM   256
#define QDIM   256
#define BDIM   256

// ---------------- device scratch (no allocations allowed) ----------------
__device__ float g_relWr [NREL * HDIM];
__device__ float g_relWqr[NREL * HDIM];
__device__ float g_relC2 [NREL * HDIM];
__device__ float g_qdot  [BDIM];
__device__ float g_NHW   [(size_t)NNODES * HDIM];
__device__ float g_EW1   [(size_t)NENT   * HDIM];
__device__ float g_agg   [(size_t)NNEW * 2 * EDIM];
__device__ float g_hprev [(size_t)NNEW * HDIM];
__device__ float g_GX    [(size_t)NNEW * 3 * HDIM];
__device__ float g_GH    [(size_t)NNEW * 3 * HDIM];
__device__ float g_hnew  [(size_t)NNEW * HDIM];
__device__ float g_HN3   [(size_t)NNEW * HDIM];
// transposed weights [N, K]
__device__ float g_WsT   [HDIM * HDIM];
__device__ float g_We2hT [HDIM * EDIM];
__device__ float g_c1T   [HDIM * EDIM];
__device__ float g_c3T   [HDIM * HDIM];

// ---------------- helpers ----------------
__device__ __forceinline__ uint32_t smem_u32(const void* p) {
    uint32_t a;
    asm("{ .reg .u64 t; cvta.to.shared.u64 t, %1; cvt.u32.u64 %0, t; }" : "=r"(a) : "l"(p));
    return a;
}

__device__ __forceinline__ void ldmx4(uint32_t addr, uint32_t& r0, uint32_t& r1,
                                      uint32_t& r2, uint32_t& r3) {
    asm volatile("ldmatrix.sync.aligned.m8n8.x4.shared.b16 {%0,%1,%2,%3}, [%4];"
                 : "=r"(r0), "=r"(r1), "=r"(r2), "=r"(r3) : "r"(addr));
}

__device__ __forceinline__ void mma16816(float* c, const uint32_t* a,
                                         uint32_t b0, uint32_t b1) {
    asm volatile(
        "mma.sync.aligned.m16n8k16.row.col.f32.bf16.bf16.f32 "
        "{%0,%1,%2,%3}, {%4,%5,%6,%7}, {%8,%9}, {%0,%1,%2,%3};"
        : "+f"(c[0]), "+f"(c[1]), "+f"(c[2]), "+f"(c[3])
        : "r"(a[0]), "r"(a[1]), "r"(a[2]), "r"(a[3]), "r"(b0), "r"(b1));
}

__device__ __forceinline__ void split_hilo(float4 v, uint2& hi, uint2& lo) {
    __nv_bfloat16 hx = __float2bfloat16_rn(v.x), hy = __float2bfloat16_rn(v.y);
    __nv_bfloat16 hz = __float2bfloat16_rn(v.z), hw = __float2bfloat16_rn(v.w);
    __nv_bfloat162 h01; h01.x = hx; h01.y = hy;
    __nv_bfloat162 h23; h23.x = hz; h23.y = hw;
    __nv_bfloat162 l01, l23;
    l01.x = __float2bfloat16_rn(v.x - __bfloat162float(hx));
    l01.y = __float2bfloat16_rn(v.y - __bfloat162float(hy));
    l23.x = __float2bfloat16_rn(v.z - __bfloat162float(hz));
    l23.y = __float2bfloat16_rn(v.w - __bfloat162float(hw));
    hi = make_uint2(*(uint32_t*)&h01, *(uint32_t*)&h23);
    lo = make_uint2(*(uint32_t*)&l01, *(uint32_t*)&l23);
}

// ---------------- HMMA bf16x3 GEMM ----------------
// C[M,N] = epi(A[M,K] (opt gather) @ Bt[N,K]^T), fp32 in/out.
// Block 128x128x32, 8 warps (4M x 2N), warp 32x64.
// EPI: 0 none, 1 +bias[col], 2 lrelu(x+bias[col])
#define ASTRIDE 40   // bf16 elems per smem row (80 B) -> conflict-free ldmatrix

template <int EPI, bool GATHER>
__global__ __launch_bounds__(256, 2)
void hmma_gemm(const float* __restrict__ A, const float* __restrict__ Bt,
               const float* __restrict__ bias, float* __restrict__ C,
               int M, int N, int K, const int* __restrict__ gidx)
{
    __shared__ __align__(16) __nv_bfloat16 sAh[128 * ASTRIDE];
    __shared__ __align__(16) __nv_bfloat16 sAl[128 * ASTRIDE];
    __shared__ __align__(16) __nv_bfloat16 sBh[128 * ASTRIDE];
    __shared__ __align__(16) __nv_bfloat16 sBl[128 * ASTRIDE];

    const int tid = threadIdx.x;
    const int wid = tid >> 5, lane = tid & 31;
    const int bx = blockIdx.x, by = blockIdx.y;
    const int wm = (wid & 3) * 32;     // warp M offset
    const int wn = (wid >> 2) * 64;    // warp N offset

    float acc[2][8][4];
#pragma unroll
    for (int i = 0; i < 2; i++)
#pragma unroll
        for (int j = 0; j < 8; j++)
#pragma unroll
            for (int u = 0; u < 4; u++) acc[i][j][u] = 0.f;

    // ---- global load setup: 128x32 fp32 tile, 4 float4 per thread ----
    const float* aptr[4]; bool av[4]; int asoff[4];
    const float* bptr[4]; int bsoff[4];
#pragma unroll
    for (int i = 0; i < 4; i++) {
        int idx = tid + 256 * i;
        int row = idx >> 3, c4 = (idx & 7) * 4;
        int grow = by * 128 + row;
        av[i] = (grow < M);
        size_t phys = 0;
        if (av[i]) phys = GATHER ? (size_t)gidx[grow] : (size_t)grow;
        aptr[i] = A + phys * (size_t)K + c4;
        asoff[i] = row * ASTRIDE + c4;
        bptr[i] = Bt + (size_t)(bx * 128 + row) * K + c4;
        bsoff[i] = row * ASTRIDE + c4;
    }

    // ---- ldmatrix per-lane smem addresses ----
    const int lrow = lane & 15;
    const int lk   = (lane >> 4) << 3;
    const uint32_t aAddrH = smem_u32(sAh) + (uint32_t)((wm + lrow) * ASTRIDE + lk) * 2;
    const uint32_t aAddrL = smem_u32(sAl) + (uint32_t)((wm + lrow) * ASTRIDE + lk) * 2;
    const int brow = (lane & 7) + ((lane >> 4) << 3);
    const int bk   = ((lane >> 3) & 1) << 3;
    const uint32_t bAddrH = smem_u32(sBh) + (uint32_t)((wn + brow) * ASTRIDE + bk) * 2;
    const uint32_t bAddrL = smem_u32(sBl) + (uint32_t)((wn + brow) * ASTRIDE + bk) * 2;

    for (int k0 = 0; k0 < K; k0 += 32) {
#pragma unroll
        for (int i = 0; i < 4; i++) {
            float4 v = make_float4(0.f, 0.f, 0.f, 0.f);
            if (av[i]) v = *(const float4*)(aptr[i] + k0);
            uint2 hi, lo; split_hilo(v, hi, lo);
            *(uint2*)&sAh[asoff[i]] = hi;
            *(uint2*)&sAl[asoff[i]] = lo;
            float4 w = *(const float4*)(bptr[i] + k0);
            split_hilo(w, hi, lo);
            *(uint2*)&sBh[bsoff[i]] = hi;
            *(uint2*)&sBl[bsoff[i]] = lo;
        }
        __syncthreads();

#pragma unroll
        for (int ks = 0; ks < 32; ks += 16) {
            uint32_t ah[2][4], al[2][4];
#pragma unroll
            for (int mi = 0; mi < 2; mi++) {
                uint32_t off = (uint32_t)(mi * 16 * ASTRIDE + ks) * 2;
                ldmx4(aAddrH + off, ah[mi][0], ah[mi][1], ah[mi][2], ah[mi][3]);
                ldmx4(aAddrL + off, al[mi][0], al[mi][1], al[mi][2], al[mi][3]);
            }
#pragma unroll
            for (int nj = 0; nj < 4; nj++) {
                uint32_t off = (uint32_t)(nj * 16 * ASTRIDE + ks) * 2;
                uint32_t bh[4], bl[4];
                ldmx4(bAddrH + off, bh[0], bh[1], bh[2], bh[3]);
                ldmx4(bAddrL + off, bl[0], bl[1], bl[2], bl[3]);
#pragma unroll
                for (int mi = 0; mi < 2; mi++) {
#pragma unroll
                    for (int h = 0; h < 2; h++) {
                        float* c = acc[mi][nj * 2 + h];
                        mma16816(c, ah[mi], bh[h * 2], bh[h * 2 + 1]);
                        mma16816(c, al[mi], bh[h * 2], bh[h * 2 + 1]);
                        mma16816(c, ah[mi], bl[h * 2], bl[h * 2 + 1]);
                    }
                }
            }
        }
        __syncthreads();
    }

    // ---- epilogue: fragments -> gmem (float2 per thread) ----
    const int g = lane >> 2, tig = lane & 3;
#pragma unroll
    for (int mi = 0; mi < 2; mi++) {
        const int r0 = by * 128 + wm + mi * 16 + g;
        const int r1 = r0 + 8;
#pragma unroll
        for (int nj = 0; nj < 8; nj++) {
            const int col = bx * 128 + wn + nj * 8 + 2 * tig;
            float b0 = 0.f, b1 = 0.f;
            if (EPI >= 1) { b0 = bias[col]; b1 = bias[col + 1]; }
            float* c = acc[mi][nj];
            if (r0 < M) {
                float x0 = c[0] + b0, x1 = c[1] + b1;
                if (EPI == 2) {
                    x0 = (x0 > 0.f) ? x0 : 0.01f * x0;
                    x1 = (x1 > 0.f) ? x1 : 0.01f * x1;
                }
                if (EPI == 0) { x0 = c[0]; x1 = c[1]; }
                *(float2*)&C[(size_t)r0 * N + col] = make_float2(x0, x1);
            }
            if (r1 < M) {
                float x2 = c[2] + b0, x3 = c[3] + b1;
                if (EPI == 2) {
                    x2 = (x2 > 0.f) ? x2 : 0.01f * x2;
                    x3 = (x3 > 0.f) ? x3 : 0.01f * x3;
                }
                if (EPI == 0) { x2 = c[2]; x3 = c[3]; }
                *(float2*)&C[(size_t)r1 * N + col] = make_float2(x2, x3);
            }
        }
    }
}

// ---------------- weight transpose: out[n*K+k] = in[k*N+n] ----------------
__global__ void transpose_kernel(const float* __restrict__ in, float* __restrict__ out,
                                 int K, int N)
{
    __shared__ float t[32][33];
    const int tx = threadIdx.x & 31, ty = threadIdx.x >> 5;
    const int n0 = blockIdx.x * 32, k0 = blockIdx.y * 32;
#pragma unroll
    for (int i = 0; i < 32; i += 8)
        t[ty + i][tx] = in[(size_t)(k0 + ty + i) * N + n0 + tx];
    __syncthreads();
#pragma unroll
    for (int i = 0; i < 32; i += 8)
        out[(size_t)(n0 + ty + i) * K + k0 + tx] = t[tx][ty + i];
}

// ---------------- small precompute kernels ----------------
__global__ void rel_precompute(const float* __restrict__ rel_emb,
                               const float* __restrict__ Wr,
                               const float* __restrict__ Wqr,
                               const float* __restrict__ candW,
                               const float* __restrict__ cand_b)
{
    const int r = blockIdx.x;
    const int j = threadIdx.x;
    __shared__ float re[EDIM];
    if (j < EDIM) re[j] = rel_emb[r * EDIM + j];
    __syncthreads();
    float s1 = 0.f, s2 = 0.f, s3 = 0.f;
#pragma unroll 4
    for (int k = 0; k < EDIM; k++) {
        const float rv = re[k];
        s1 = fmaf(rv, Wr[k * HDIM + j], s1);
        s2 = fmaf(rv, Wqr[k * HDIM + j], s2);
        s3 = fmaf(rv, candW[(EDIM + k) * HDIM + j], s3);
    }
    g_relWr[r * HDIM + j]  = s1;
    g_relWqr[r * HDIM + j] = s2;
    g_relC2[r * HDIM + j]  = s3 + cand_b[j];
}

__global__ void qdot_kernel(const float* __restrict__ qrep,
                            const float* __restrict__ rankW)
{
    const int b = blockIdx.x * 8 + (threadIdx.x >> 5);
    const int lane = threadIdx.x & 31;
    if (b >= BDIM) return;
    float s = 0.f;
#pragma unroll
    for (int i = 0; i < 8; i++) {
        int q = lane + 32 * i;
        s = fmaf(qrep[b * QDIM + q], rankW[HDIM + q], s);
    }
#pragma unroll
    for (int o = 16; o > 0; o >>= 1) s += __shfl_xor_sync(0xffffffffu, s, o);
    if (lane == 0) g_qdot[b] = s;
}

__global__ void zero_agg_kernel()
{
    const size_t n4 = (size_t)NNEW * 2 * EDIM / 4;
    size_t i = (size_t)blockIdx.x * blockDim.x + threadIdx.x;
    if (i < n4) ((float4*)g_agg)[i] = make_float4(0.f, 0.f, 0.f, 0.f);
}

// ---------------- per-edge attention + scatter ----------------
__global__ __launch_bounds__(256)
void edge_alpha_scatter(const float* __restrict__ rel_emb,
                        const float* __restrict__ ent_emb,
                        const float* __restrict__ bqr,
                        const float* __restrict__ w_alpha,
                        const float* __restrict__ b_alpha,
                        const int* __restrict__ head,
                        const int* __restrict__ erel,
                        const int* __restrict__ qrel,
                        const int* __restrict__ tent,
                        const int* __restrict__ tnode)
{
    const int m = blockIdx.x * 8 + (threadIdx.x >> 5);
    if (m >= MEDGE) return;
    const int lane = threadIdx.x & 31;
    const int h = head[m], r = erel[m], q = qrel[m];
    const int te = tent[m], t = tnode[m];

    const float* nh = g_NHW   + (size_t)h * HDIM;
    const float* rw = g_relWr + r * HDIM;
    const float* rq = g_relWqr + q * HDIM;

    float s = 0.f;
#pragma unroll
    for (int i = 0; i < 8; i++) {
        int j = lane + 32 * i;
        float f = nh[j] + rw[j] + rq[j] + bqr[j];
        f = fmaxf(f, 0.f);
        s = fmaf(f, w_alpha[j], s);
    }
#pragma unroll
    for (int o = 16; o > 0; o >>= 1) s += __shfl_xor_sync(0xffffffffu, s, o);
    const float alpha = 1.f / (1.f + __expf(-(s + b_alpha[0])));

    const float* hr  = rel_emb + r * EDIM;
    const float* tev = ent_emb + (size_t)te * EDIM;
    float* aggp = g_agg + (size_t)t * (2 * EDIM);
#pragma unroll
    for (int i = 0; i < 4; i++) {
        int j = lane + 32 * i;
        atomicAdd(&aggp[j],        hr[j]  * alpha);
        atomicAdd(&aggp[EDIM + j], tev[j] * alpha);
    }
}

// ---------------- GRU gates + LayerNorm ----------------
__global__ __launch_bounds__(256)
void gru_ln_kernel(const float* __restrict__ ln_g, const float* __restrict__ ln_b)
{
    const int n = blockIdx.x;
    const int j = threadIdx.x;
    const size_t o3 = (size_t)n * 3 * HDIM;

    const float xr = g_GX[o3 + j];
    const float xz = g_GX[o3 + HDIM + j];
    const float xn = g_GX[o3 + 2 * HDIM + j];
    const float hr = g_GH[o3 + j];
    const float hz = g_GH[o3 + HDIM + j];
    const float hn = g_GH[o3 + 2 * HDIM + j];
    const float hp = g_hprev[(size_t)n * HDIM + j];

    const float rg = 1.f / (1.f + __expf(-(xr + hr)));
    const float zg = 1.f / (1.f + __expf(-(xz + hz)));
    const float ng = tanhf(xn + rg * hn);
    const float h  = (1.f - zg) * ng + zg * hp;

    __shared__ float rs1[8], rs2[8];
    float s1 = h, s2 = h * h;
#pragma unroll
    for (int o = 16; o > 0; o >>= 1) {
        s1 += __shfl_xor_sync(0xffffffffu, s1, o);
        s2 += __shfl_xor_sync(0xffffffffu, s2, o);
    }
    const int wid = threadIdx.x >> 5, lane = threadIdx.x & 31;
    if (lane == 0) { rs1[wid] = s1; rs2[wid] = s2; }
    __syncthreads();
    if (wid == 0) {
        float a = (lane < 8) ? rs1[lane] : 0.f;
        float b = (lane < 8) ? rs2[lane] : 0.f;
#pragma unroll
        for (int o = 4; o > 0; o >>= 1) {
            a += __shfl_xor_sync(0xffffffffu, a, o);
            b += __shfl_xor_sync(0xffffffffu, b, o);
        }
        if (lane == 0) { rs1[0] = a; rs2[0] = b; }
    }
    __syncthreads();
    const float mu  = rs1[0] * (1.f / HDIM);
    const float var = rs2[0] * (1.f / HDIM) - mu * mu;
    const float inv = rsqrtf(var + 1e-5f);
    g_hnew[(size_t)n * HDIM + j] = (h - mu) * inv * ln_g[j] + ln_b[j];
}

// ---------------- final per-edge scoring ----------------
__global__ __launch_bounds__(256)
void edge_score(const int* __restrict__ erel,
                const int* __restrict__ tent,
                const int* __restrict__ tnode,
                const int* __restrict__ bidx,
                const float* __restrict__ rankW,
                const float* __restrict__ rank_b,
                float* __restrict__ out)
{
    const int m = blockIdx.x * 8 + (threadIdx.x >> 5);
    if (m >= MEDGE) return;
    const int lane = threadIdx.x & 31;
    const int r = erel[m], te = tent[m], t = tnode[m], b = bidx[m];

    const float* e1 = g_EW1   + (size_t)te * HDIM;
    const float* c2 = g_relC2 + r * HDIM;
    const float* h3 = g_HN3   + (size_t)t * HDIM;

    float s = 0.f;
#pragma unroll
    for (int i = 0; i < 8; i++) {
        int j = lane + 32 * i;
        float v = e1[j] + c2[j] + h3[j];
        v = (v > 0.f) ? v : 0.01f * v;
        s = fmaf(v, rankW[j], s);
    }
#pragma unroll
    for (int o = 16; o > 0; o >>= 1) s += __shfl_xor_sync(0xffffffffu, s, o);
    if (lane == 0) out[m] = s + g_qdot[b] + rank_b[0];
}

// ---------------- launcher ----------------
extern "C" void kernel_launch(void* const* d_in, const int* in_sizes, int n_in,
                              void* d_out, int out_size)
{
    const float* entity_emb   = (const float*)d_in[0];
    const float* relation_emb = (const float*)d_in[1];
    const float* node_hidden  = (const float*)d_in[2];
    const float* query_repr   = (const float*)d_in[3];
    const float* Ws           = (const float*)d_in[4];
    const float* Wr           = (const float*)d_in[5];
    const float* Wqr          = (const float*)d_in[6];
    const float* bqr          = (const float*)d_in[7];
    const float* w_alpha      = (const float*)d_in[8];
    const float* b_alpha      = (const float*)d_in[9];
    const float* W_ih         = (const float*)d_in[10];
    const float* W_hh         = (const float*)d_in[11];
    const float* b_ih         = (const float*)d_in[12];
    const float* b_hh         = (const float*)d_in[13];
    const float* We2h_W       = (const float*)d_in[14];
    const float* We2h_b       = (const float*)d_in[15];
    const float* cand_W       = (const float*)d_in[16];
    const float* cand_b       = (const float*)d_in[17];
    const float* rank_W       = (const float*)d_in[18];
    const float* rank_b       = (const float*)d_in[19];
    const float* ln_g         = (const float*)d_in[20];
    const float* ln_b         = (const float*)d_in[21];
    const int* head_node      = (const int*)d_in[22];
    const int* edge_rel       = (const int*)d_in[23];
    const int* tail_ent       = (const int*)d_in[24];
    const int* tail_node      = (const int*)d_in[25];
    const int* query_rel      = (const int*)d_in[26];
    const int* batch_idx      = (const int*)d_in[27];
    const int* tail_node_ent  = (const int*)d_in[28];
    float* scores = (float*)d_out;

    float *p_NHW, *p_EW1, *p_agg, *p_hprev, *p_GX, *p_GH, *p_hnew, *p_HN3;
    float *p_WsT, *p_We2hT, *p_c1T, *p_c3T;
    cudaGetSymbolAddress((void**)&p_NHW,   g_NHW);
    cudaGetSymbolAddress((void**)&p_EW1,   g_EW1);
    cudaGetSymbolAddress((void**)&p_agg,   g_agg);
    cudaGetSymbolAddress((void**)&p_hprev, g_hprev);
    cudaGetSymbolAddress((void**)&p_GX,    g_GX);
    cudaGetSymbolAddress((void**)&p_GH,    g_GH);
    cudaGetSymbolAddress((void**)&p_hnew,  g_hnew);
    cudaGetSymbolAddress((void**)&p_HN3,   g_HN3);
    cudaGetSymbolAddress((void**)&p_WsT,   g_WsT);
    cudaGetSymbolAddress((void**)&p_We2hT, g_We2hT);
    cudaGetSymbolAddress((void**)&p_c1T,   g_c1T);
    cudaGetSymbolAddress((void**)&p_c3T,   g_c3T);

    // 1. independent precompute
    zero_agg_kernel<<<(NNEW * 2 * EDIM / 4 + 255) / 256, 256>>>();
    transpose_kernel<<<dim3(HDIM / 32, HDIM / 32), 256>>>(Ws, p_WsT, HDIM, HDIM);
    transpose_kernel<<<dim3(HDIM / 32, EDIM / 32), 256>>>(We2h_W, p_We2hT, EDIM, HDIM);
    transpose_kernel<<<dim3(HDIM / 32, EDIM / 32), 256>>>(cand_W, p_c1T, EDIM, HDIM);
    transpose_kernel<<<dim3(HDIM / 32, HDIM / 32), 256>>>(cand_W + 2 * EDIM * HDIM, p_c3T, HDIM, HDIM);
    rel_precompute<<<NREL, 256>>>(relation_emb, Wr, Wqr, cand_W, cand_b);
    qdot_kernel<<<BDIM / 8, 256>>>(query_repr, rank_W);

    // 2. tensor-core GEMMs (HMMA bf16x3)
    hmma_gemm<0, false><<<dim3(2, (NNODES + 127) / 128), 256>>>(
        node_hidden, p_WsT, nullptr, p_NHW, NNODES, HDIM, HDIM, nullptr);
    hmma_gemm<0, false><<<dim3(2, (NENT + 127) / 128), 256>>>(
        entity_emb, p_c1T, nullptr, p_EW1, NENT, HDIM, EDIM, nullptr);
    hmma_gemm<2, true><<<dim3(2, (NNEW + 127) / 128), 256>>>(
        entity_emb, p_We2hT, We2h_b, p_hprev, NNEW, HDIM, EDIM, tail_node_ent);

    // 3. per-edge attention + scatter into agg
    edge_alpha_scatter<<<(MEDGE + 7) / 8, 256>>>(
        relation_emb, entity_emb, bqr, w_alpha, b_alpha,
        head_node, edge_rel, query_rel, tail_ent, tail_node);

    // 4. GRU GEMMs (W_ih/W_hh torch layout is already [N,K])
    hmma_gemm<1, false><<<dim3(6, (NNEW + 127) / 128), 256>>>(
        p_agg, W_ih, b_ih, p_GX, NNEW, 3 * HDIM, 2 * EDIM, nullptr);
    hmma_gemm<1, false><<<dim3(6, (NNEW + 127) / 128), 256>>>(
        p_hprev, W_hh, b_hh, p_GH, NNEW, 3 * HDIM, HDIM, nullptr);

    // 5. gates + LayerNorm
    gru_ln_kernel<<<NNEW, 256>>>(ln_g, ln_b);

    // 6. HN3 = h_new @ cand_W[2E:]
    hmma_gemm<0, false><<<dim3(2, (NNEW + 127) / 128), 256>>>(
        p_hnew, p_c3T, nullptr, p_HN3, NNEW, HDIM, HDIM, nullptr);

    // 7. final scores
    edge_score<<<(MEDGE + 7) / 8, 256>>>(
        edge_rel, tail_ent, tail_node, batch_idx, rank_W, rank_b, scores);
}